// round 15
// baseline (speedup 1.0000x reference)
#include <cuda_runtime.h>
#include <cuda_bf16.h>
#include <math.h>

// B=32, S=32, N=128, U=64, E=2, L=2, N_STEPS=3, NC=5
typedef unsigned long long ULL;

// Scratch (allocation-free)
__device__ float g_h[32 * 128 * 64];     // hidden state, per batch
__device__ float g_part[32 * 4 * 5];     // per-CTA partial logit maxima
__device__ float g_Wi[16 * 4096];        // interleaved weights: [m][k2*128 + c*2 + p]

// ---------------- packed f32x2 helpers ----------------
__device__ __forceinline__ ULL pk2(float a, float b) {
    ULL r; asm("mov.b64 %0,{%1,%2};" : "=l"(r) : "f"(a), "f"(b)); return r;
}
__device__ __forceinline__ float2 upk2(ULL v) {
    float2 f; asm("mov.b64 {%0,%1},%2;" : "=f"(f.x), "=f"(f.y) : "l"(v)); return f;
}
__device__ __forceinline__ void fma2(ULL& d, ULL a, ULL b) {
    asm("fma.rn.f32x2 %0,%1,%2,%0;" : "+l"(d) : "l"(a), "l"(b));
}
__device__ __forceinline__ float red2(ULL v) { float2 f = upk2(v); return f.x + f.y; }
__device__ __forceinline__ float sigf(float x) { return 1.0f / (1.0f + expf(-x)); }

// smem layout (float offsets)
#define OFF_SHI 0          // interleaved h  [64 k2][128]      8192
#define OFF_SA  8192       // A slice [2][32][132]             8448
#define OFF_SHO 16640      // own h rows [32][68]              2176
#define OFF_SM0 18816      // [32][68]                         2176
#define OFF_SM1 20992      // [32][68]                         2176
#define OFF_SAa 23168      // [32][68]                         2176
#define OFF_SW0 25344      // weight buf 0 (interleaved)       4096
#define OFF_SW1 29440      // weight buf 1                     4096
#define SMEM_FLOATS 33536
#define SMEM_BYTES (SMEM_FLOATS * 4)

__device__ __forceinline__ void cpa16(float* s, const float* g) {
    unsigned a = (unsigned)__cvta_generic_to_shared(s);
    asm volatile("cp.async.cg.shared.global [%0], [%1], 16;" :: "r"(a), "l"(g));
}
#define CP_COMMIT() asm volatile("cp.async.commit_group;" ::: "memory")
#define CP_WAIT(n)  asm volatile("cp.async.wait_group %0;" :: "n"(n) : "memory")

__device__ __forceinline__ void prefW(float* dst, const float* src, int tid) {
    #pragma unroll
    for (int i = 0; i < 4; i++) {
        int o = (tid + i * 256) * 4;
        cpa16(dst + o, src + o);
    }
    CP_COMMIT();
}

__device__ __forceinline__ void cl_sync() {
    asm volatile("barrier.cluster.arrive.aligned;" ::: "memory");
    asm volatile("barrier.cluster.wait.aligned;" ::: "memory");
}

// acc[2][4] += (rows x0,x1, scalar contiguous) @ Wi(interleaved 64x64), k-paired
__device__ __forceinline__ void gemm8p(ULL (&acc)[2][4],
                                       const float* __restrict__ x0,
                                       const float* __restrict__ x1,
                                       const float* __restrict__ Wi, int col) {
    #pragma unroll 8
    for (int k2 = 0; k2 < 32; k2++) {
        ULL xa = *(const ULL*)(x0 + 2 * k2);
        ULL xb = *(const ULL*)(x1 + 2 * k2);
        const float* wp = Wi + k2 * 128 + col * 2;
        ulonglong2 wa = *(const ulonglong2*)(wp);       // cols col, col+1
        ulonglong2 wb = *(const ulonglong2*)(wp + 4);   // cols col+2, col+3
        fma2(acc[0][0], xa, wa.x); fma2(acc[0][1], xa, wa.y);
        fma2(acc[0][2], xa, wb.x); fma2(acc[0][3], xa, wb.y);
        fma2(acc[1][0], xb, wa.x); fma2(acc[1][1], xb, wa.y);
        fma2(acc[1][2], xb, wb.x); fma2(acc[1][3], xb, wb.y);
    }
}

__device__ __forceinline__ void bias2p(ULL (&acc)[2][4], const float* b, int col) {
    float4 v = *(const float4*)&b[col];
    acc[0][0] = acc[1][0] = pk2(v.x, 0.f);
    acc[0][1] = acc[1][1] = pk2(v.y, 0.f);
    acc[0][2] = acc[1][2] = pk2(v.z, 0.f);
    acc[0][3] = acc[1][3] = pk2(v.w, 0.f);
}

// ---------------------------------------------------------------------------
// prep: interleave 16 weight matrices (k-pairs adjacent per column)
//   g_Wi[m][(k>>1)*128 + c*2 + (k&1)] = Wsrc[k*64 + c]
// m = l*8 + {0:Wm0,1:Wm1,2:Ug0,3:Wg0,4:Ug1,5:Wg1,6:Ug2,7:Wg2}
// ---------------------------------------------------------------------------
__global__ void prep_weights(const float* __restrict__ W_msg,
                             const float* __restrict__ Wg,
                             const float* __restrict__ Ug) {
    int m = blockIdx.x, tid = threadIdx.x;
    int l = m >> 3, s = m & 7;
    const float* src;
    if (s < 2) src = W_msg + ((size_t)l * 2 + s) * 4096;
    else {
        int g = (s - 2) >> 1;
        bool isU = ((s - 2) & 1) == 0;
        src = (isU ? Ug : Wg) + ((size_t)l * 3 + g) * 4096;
    }
    float* dst = g_Wi + (size_t)m * 4096;
    #pragma unroll
    for (int i = 0; i < 4; i++) {
        int i4 = tid + i * 256;          // float4 index 0..1023
        int k = i4 >> 4, c4 = i4 & 15;
        float4 v = *(const float4*)(src + (size_t)k * 64 + c4 * 4);
        int base = (k >> 1) * 128 + (k & 1);
        dst[base + (c4 * 4 + 0) * 2] = v.x;
        dst[base + (c4 * 4 + 1) * 2] = v.y;
        dst[base + (c4 * 4 + 2) * 2] = v.z;
        dst[base + (c4 * 4 + 3) * 2] = v.w;
    }
}

// ---------------------------------------------------------------------------
__global__ void __cluster_dims__(4, 1, 1) __launch_bounds__(256, 1)
ggnn_all(const float* __restrict__ input_seq,
         const int* __restrict__ seq_lengths,
         const float* __restrict__ Adj,
         const float* __restrict__ b_msg,
         const float* __restrict__ bg,
         const float* __restrict__ fc_w,
         const float* __restrict__ fc_b,
         float* __restrict__ out)
{
    extern __shared__ float sm[];
    float* shi = sm + OFF_SHI;
    float* sA  = sm + OFF_SA;
    float* sho = sm + OFF_SHO;
    float* sM0 = sm + OFF_SM0;
    float* sM1 = sm + OFF_SM1;
    float* sa  = sm + OFF_SAa;
    float* sW0 = sm + OFF_SW0;
    float* sW1 = sm + OFF_SW1;

    const int tid   = threadIdx.x;
    const int rg    = tid >> 4;          // 0..15 -> rows rg, rg+16
    const int col   = (tid & 15) * 4;    // 4 cols
    const int b     = blockIdx.x >> 2;
    const int crank = blockIdx.x & 3;
    const int r0    = crank * 32;

    // ---------------- prologue ----------------
    {
        int idx = seq_lengths[b] - 1;
        idx = idx < 0 ? 0 : (idx > 31 ? 31 : idx);
        const float* src = input_seq + ((size_t)(b * 32 + idx)) * 8192 + (size_t)r0 * 64;
        float* dst = g_h + (size_t)b * 8192 + (size_t)r0 * 64;
        #pragma unroll
        for (int i = 0; i < 2; i++) {
            int i4 = tid + i * 256;              // 0..511: n = i4>>4, u4 = i4&15
            int n = i4 >> 4, u4 = i4 & 15;
            float4 v = *(const float4*)(src + (size_t)n * 64 + u4 * 4);
            __stcg((float4*)(dst + (size_t)n * 64 + u4 * 4), v);
            *(float4*)&sho[n * 68 + u4 * 4] = v;
        }
        // A[b][e][r0+r][:] -> sA[(e*32+r)*132 + k]
        #pragma unroll
        for (int i = 0; i < 8; i++) {
            int i4 = tid + i * 256;
            int e = i4 >> 10, r = (i4 >> 5) & 31, c4 = i4 & 31;
            float4 v = *(const float4*)(Adj +
                       (((size_t)b * 2 + e) * 128 + r0 + r) * 128 + c4 * 4);
            *(float4*)&sA[(e * 32 + r) * 132 + c4 * 4] = v;
        }
    }

    float4 hn0, hn1;

    for (int l = 0; l < 2; l++) {
        const float* Wi  = g_Wi + (size_t)l * 8 * 4096;
        const float* bml = b_msg + l * 64;
        const float* bgl = bg + l * 192;

        for (int s = 0; s < 3; s++) {
            // -------- h exchange across cluster --------
            __threadfence();
            cl_sync();
            __threadfence();

            prefW(sW0, Wi + 0 * 4096, tid);            // G1: Wm0
            prefW(sW1, Wi + 1 * 4096, tid);            // G2: Wm1

            {   // read full h[b], write k-pair-interleaved into shi
                const float* hb = g_h + (size_t)b * 8192;
                #pragma unroll
                for (int i = 0; i < 4; i++) {
                    int t = tid + i * 256;             // 0..1023: n2, u4
                    int n2 = t >> 4, u4 = t & 15;
                    float4 v0 = __ldcg((const float4*)(hb + (size_t)(2 * n2) * 64 + u4 * 4));
                    float4 v1 = __ldcg((const float4*)(hb + (size_t)(2 * n2 + 1) * 64 + u4 * 4));
                    float* d = shi + n2 * 128 + u4 * 8;
                    *(ULL*)(d + 0) = pk2(v0.x, v1.x);
                    *(ULL*)(d + 2) = pk2(v0.y, v1.y);
                    *(ULL*)(d + 4) = pk2(v0.z, v1.z);
                    *(ULL*)(d + 6) = pk2(v0.w, v1.w);
                }
            }
            __syncthreads();                            // shi visible

            // -------- msgmm: M_e = A_e @ h, packed along k --------
            {
                ULL acc[2][2][4] = {};                  // [edge][row][col]
                #pragma unroll 4
                for (int k2 = 0; k2 < 64; k2++) {
                    ULL a00 = *(const ULL*)&sA[rg * 132 + 2 * k2];
                    ULL a01 = *(const ULL*)&sA[(32 + rg) * 132 + 2 * k2];
                    ULL a10 = *(const ULL*)&sA[(16 + rg) * 132 + 2 * k2];
                    ULL a11 = *(const ULL*)&sA[(48 + rg) * 132 + 2 * k2];
                    const float* wp = shi + k2 * 128 + col * 2;
                    ulonglong2 wa = *(const ulonglong2*)(wp);
                    ulonglong2 wb = *(const ulonglong2*)(wp + 4);
                    fma2(acc[0][0][0], a00, wa.x); fma2(acc[0][0][1], a00, wa.y);
                    fma2(acc[0][0][2], a00, wb.x); fma2(acc[0][0][3], a00, wb.y);
                    fma2(acc[1][0][0], a01, wa.x); fma2(acc[1][0][1], a01, wa.y);
                    fma2(acc[1][0][2], a01, wb.x); fma2(acc[1][0][3], a01, wb.y);
                    fma2(acc[0][1][0], a10, wa.x); fma2(acc[0][1][1], a10, wa.y);
                    fma2(acc[0][1][2], a10, wb.x); fma2(acc[0][1][3], a10, wb.y);
                    fma2(acc[1][1][0], a11, wa.x); fma2(acc[1][1][1], a11, wa.y);
                    fma2(acc[1][1][2], a11, wb.x); fma2(acc[1][1][3], a11, wb.y);
                }
                *(float4*)&sM0[rg * 68 + col] = make_float4(
                    red2(acc[0][0][0]), red2(acc[0][0][1]), red2(acc[0][0][2]), red2(acc[0][0][3]));
                *(float4*)&sM1[rg * 68 + col] = make_float4(
                    red2(acc[1][0][0]), red2(acc[1][0][1]), red2(acc[1][0][2]), red2(acc[1][0][3]));
                *(float4*)&sM0[(rg + 16) * 68 + col] = make_float4(
                    red2(acc[0][1][0]), red2(acc[0][1][1]), red2(acc[0][1][2]), red2(acc[0][1][3]));
                *(float4*)&sM1[(rg + 16) * 68 + col] = make_float4(
                    red2(acc[1][1][0]), red2(acc[1][1][1]), red2(acc[1][1][2]), red2(acc[1][1][3]));
            }
            CP_WAIT(1); __syncthreads();                // sM visible, W0 (Wm0) ready

            const float* hx0 = &sho[rg * 68];
            const float* hx1 = &sho[(rg + 16) * 68];
            float4 h0v = *(const float4*)&sho[rg * 68 + col];
            float4 h1v = *(const float4*)&sho[(rg + 16) * 68 + col];

            // -------- a = M0@W0 + M1@W1 + b_msg --------
            ULL accA[2][4];
            bias2p(accA, bml, col);
            gemm8p(accA, &sM0[rg * 68], &sM0[(rg + 16) * 68], sW0, col);
            __syncthreads();  prefW(sW0, Wi + 2 * 4096, tid);   // G3: Ug0
            CP_WAIT(1); __syncthreads();                        // W1 (Wm1) ready
            gemm8p(accA, &sM1[rg * 68], &sM1[(rg + 16) * 68], sW1, col);
            *(float4*)&sa[rg * 68 + col] = make_float4(
                red2(accA[0][0]), red2(accA[0][1]), red2(accA[0][2]), red2(accA[0][3]));
            *(float4*)&sa[(rg + 16) * 68 + col] = make_float4(
                red2(accA[1][0]), red2(accA[1][1]), red2(accA[1][2]), red2(accA[1][3]));
            __syncthreads();  prefW(sW1, Wi + 3 * 4096, tid);   // G4: Wg0
            CP_WAIT(1); __syncthreads();                        // Ug0 ready, sa visible

            // -------- z = sigmoid(a@Wg0 + h@Ug0 + bg0) --------
            ULL accZ[2][4];
            bias2p(accZ, bgl, col);
            gemm8p(accZ, hx0, hx1, sW0, col);
            __syncthreads();  prefW(sW0, Wi + 4 * 4096, tid);   // G5: Ug1
            CP_WAIT(1); __syncthreads();                        // Wg0 ready
            gemm8p(accZ, &sa[rg * 68], &sa[(rg + 16) * 68], sW1, col);
            float z[2][4];
            #pragma unroll
            for (int j = 0; j < 4; j++) {
                z[0][j] = sigf(red2(accZ[0][j]));
                z[1][j] = sigf(red2(accZ[1][j]));
            }
            __syncthreads();  prefW(sW1, Wi + 5 * 4096, tid);   // G6: Wg1
            CP_WAIT(1); __syncthreads();                        // Ug1 ready

            // -------- r = sigmoid(a@Wg1 + h@Ug1 + bg1); rh = r*h --------
            ULL accR[2][4];
            bias2p(accR, bgl + 64, col);
            gemm8p(accR, hx0, hx1, sW0, col);
            __syncthreads();  prefW(sW0, Wi + 6 * 4096, tid);   // G7: Ug2
            CP_WAIT(1); __syncthreads();                        // Wg1 ready
            gemm8p(accR, &sa[rg * 68], &sa[(rg + 16) * 68], sW1, col);
            {
                float r00 = sigf(red2(accR[0][0])), r01 = sigf(red2(accR[0][1]));
                float r02 = sigf(red2(accR[0][2])), r03 = sigf(red2(accR[0][3]));
                float r10 = sigf(red2(accR[1][0])), r11 = sigf(red2(accR[1][1]));
                float r12 = sigf(red2(accR[1][2])), r13 = sigf(red2(accR[1][3]));
                *(float4*)&sM0[rg * 68 + col] =
                    make_float4(r00 * h0v.x, r01 * h0v.y, r02 * h0v.z, r03 * h0v.w);
                *(float4*)&sM0[(rg + 16) * 68 + col] =
                    make_float4(r10 * h1v.x, r11 * h1v.y, r12 * h1v.z, r13 * h1v.w);
            }
            __syncthreads();  prefW(sW1, Wi + 7 * 4096, tid);   // G8: Wg2
            CP_WAIT(1); __syncthreads();                        // Ug2 ready, rh visible

            // -------- c = tanh(a@Wg2 + rh@Ug2 + bg2); h = (1-z)h + z c ----
            ULL accC[2][4];
            bias2p(accC, bgl + 128, col);
            gemm8p(accC, &sM0[rg * 68], &sM0[(rg + 16) * 68], sW0, col);
            CP_WAIT(0); __syncthreads();                        // Wg2 ready
            gemm8p(accC, &sa[rg * 68], &sa[(rg + 16) * 68], sW1, col);

            hn0 = make_float4(
                (1.0f - z[0][0]) * h0v.x + z[0][0] * tanhf(red2(accC[0][0])),
                (1.0f - z[0][1]) * h0v.y + z[0][1] * tanhf(red2(accC[0][1])),
                (1.0f - z[0][2]) * h0v.z + z[0][2] * tanhf(red2(accC[0][2])),
                (1.0f - z[0][3]) * h0v.w + z[0][3] * tanhf(red2(accC[0][3])));
            hn1 = make_float4(
                (1.0f - z[1][0]) * h1v.x + z[1][0] * tanhf(red2(accC[1][0])),
                (1.0f - z[1][1]) * h1v.y + z[1][1] * tanhf(red2(accC[1][1])),
                (1.0f - z[1][2]) * h1v.z + z[1][2] * tanhf(red2(accC[1][2])),
                (1.0f - z[1][3]) * h1v.w + z[1][3] * tanhf(red2(accC[1][3])));

            // own rows: update smem tile + publish to gmem for the exchange
            float* hb = g_h + (size_t)b * 8192;
            *(float4*)&sho[rg * 68 + col] = hn0;
            *(float4*)&sho[(rg + 16) * 68 + col] = hn1;
            __stcg((float4*)&hb[(r0 + rg) * 64 + col], hn0);
            __stcg((float4*)&hb[(r0 + rg + 16) * 64 + col], hn1);
        }
    }

    // ---------------- final: relu -> fc -> max over nodes -----------------
    __syncthreads();                     // drain all smem readers
    *(float4*)&sa[rg * 68 + col] = hn0;  // reuse sa as final-h tile
    *(float4*)&sa[(rg + 16) * 68 + col] = hn1;
    for (int i = tid; i < 320; i += 256) sW0[i] = fc_w[i];
    __syncthreads();

    if (tid < 160) {
        int row = tid / 5, c = tid % 5;
        float acc = fc_b[c];
        #pragma unroll 8
        for (int u = 0; u < 64; u++) {
            float v = sa[row * 68 + u];
            v = v > 0.0f ? v : 0.0f;
            acc += v * sW0[u * 5 + c];
        }
        sM1[row * 5 + c] = acc;
    }
    __syncthreads();
    if (tid < 5) {
        float m = -1e30f;
        #pragma unroll 8
        for (int r = 0; r < 32; r++) m = fmaxf(m, sM1[r * 5 + tid]);
        __stcg(&g_part[(b * 4 + crank) * 5 + tid], m);
    }
    __threadfence();
    cl_sync();
    __threadfence();
    if (crank == 0 && tid < 5) {
        float m = -1e30f;
        #pragma unroll
        for (int r = 0; r < 4; r++)
            m = fmaxf(m, __ldcg(&g_part[(b * 4 + r) * 5 + tid]));
        out[b * 5 + tid] = m;
    }
}

// ---------------------------------------------------------------------------
extern "C" void kernel_launch(void* const* d_in, const int* in_sizes, int n_in,
                              void* d_out, int out_size) {
    const float* input_seq   = (const float*)d_in[0];
    const int*   seq_lengths = (const int*)d_in[1];
    const float* Adj         = (const float*)d_in[2];
    const float* W_msg       = (const float*)d_in[3];
    const float* b_msg       = (const float*)d_in[4];
    const float* Wg          = (const float*)d_in[5];
    const float* Ug          = (const float*)d_in[6];
    const float* bg          = (const float*)d_in[7];
    const float* fc_w        = (const float*)d_in[8];
    const float* fc_b        = (const float*)d_in[9];
    float* out = (float*)d_out;

    cudaFuncSetAttribute(ggnn_all,
                         cudaFuncAttributeMaxDynamicSharedMemorySize, SMEM_BYTES);

    prep_weights<<<16, 256>>>(W_msg, Wg, Ug);
    ggnn_all<<<128, 256, SMEM_BYTES>>>(input_seq, seq_lengths, Adj,
                                       b_msg, bg, fc_w, fc_b, out);
}

// round 16
// speedup vs baseline: 1.6728x; 1.6728x over previous
#include <cuda_runtime.h>
#include <cuda_bf16.h>
#include <math.h>

// B=32, S=32, N=128, U=64, E=2, L=2, N_STEPS=3, NC=5
typedef unsigned long long ULL;

// Scratch (allocation-free)
__device__ float g_h[32 * 128 * 64];     // hidden state, per batch
__device__ float g_part[32 * 4 * 5];     // per-CTA partial logit maxima
__device__ float g_Wi[16 * 4096];        // interleaved weights: [m][k2*128 + c*2 + p]

// ---------------- packed f32x2 helpers ----------------
__device__ __forceinline__ ULL pk2(float a, float b) {
    ULL r; asm("mov.b64 %0,{%1,%2};" : "=l"(r) : "f"(a), "f"(b)); return r;
}
__device__ __forceinline__ float2 upk2(ULL v) {
    float2 f; asm("mov.b64 {%0,%1},%2;" : "=f"(f.x), "=f"(f.y) : "l"(v)); return f;
}
__device__ __forceinline__ void fma2(ULL& d, ULL a, ULL b) {
    asm("fma.rn.f32x2 %0,%1,%2,%0;" : "+l"(d) : "l"(a), "l"(b));
}
__device__ __forceinline__ float red2(ULL v) { float2 f = upk2(v); return f.x + f.y; }
__device__ __forceinline__ float fsig(float x) {
    return __fdividef(1.0f, 1.0f + __expf(-x));
}
__device__ __forceinline__ float ftanh(float x) {
    return __fdividef(2.0f, 1.0f + __expf(-2.0f * x)) - 1.0f;
}

// smem layout (float offsets)
#define OFF_SHI 0          // interleaved h  [64 k2][128]      8192
#define OFF_SA  8192       // A slice [2][32][132]             8448
#define OFF_SHO 16640      // own h rows [32][68]              2176
#define OFF_SM0 18816      // [32][68]                         2176
#define OFF_SM1 20992      // [32][68]                         2176
#define OFF_SAa 23168      // [32][68]                         2176
#define OFF_SW0 25344      // weight buf 0 (interleaved)       4096
#define OFF_SW1 29440      // weight buf 1                     4096
#define SMEM_FLOATS 33536
#define SMEM_BYTES (SMEM_FLOATS * 4)

__device__ __forceinline__ void cpa16(float* s, const float* g) {
    unsigned a = (unsigned)__cvta_generic_to_shared(s);
    asm volatile("cp.async.cg.shared.global [%0], [%1], 16;" :: "r"(a), "l"(g));
}
#define CP_COMMIT() asm volatile("cp.async.commit_group;" ::: "memory")
#define CP_WAIT(n)  asm volatile("cp.async.wait_group %0;" :: "n"(n) : "memory")

__device__ __forceinline__ void prefW(float* dst, const float* src, int tid) {
    #pragma unroll
    for (int i = 0; i < 4; i++) {
        int o = (tid + i * 256) * 4;
        cpa16(dst + o, src + o);
    }
    CP_COMMIT();
}

__device__ __forceinline__ void cl_sync() {
    asm volatile("barrier.cluster.arrive.aligned;" ::: "memory");
    asm volatile("barrier.cluster.wait.aligned;" ::: "memory");
}

// acc[4rows][2cols] += X @ W, k-paired. W interleaved [k2][c*2+p].
// Thread: rows rb0..rb3 (float offsets into t, stride-68 tiles), cols 2cg,2cg+1.
// W load = one contiguous 16B per k2 (conflict-free); x loads are broadcasts.
__device__ __forceinline__ void gemmp(ULL (&acc)[4][2], const float* __restrict__ t,
                                      int rb0, int rb1, int rb2, int rb3,
                                      const float* __restrict__ W, int cg) {
    #pragma unroll 4
    for (int k2 = 0; k2 < 32; k2 += 2) {
        ulonglong2 w0 = *(const ulonglong2*)(W + k2 * 128 + cg * 4);
        ulonglong2 w1 = *(const ulonglong2*)(W + k2 * 128 + 128 + cg * 4);
        ulonglong2 x0 = *(const ulonglong2*)(t + rb0 + 2 * k2);
        ulonglong2 x1 = *(const ulonglong2*)(t + rb1 + 2 * k2);
        ulonglong2 x2 = *(const ulonglong2*)(t + rb2 + 2 * k2);
        ulonglong2 x3 = *(const ulonglong2*)(t + rb3 + 2 * k2);
        fma2(acc[0][0], x0.x, w0.x); fma2(acc[0][1], x0.x, w0.y);
        fma2(acc[0][0], x0.y, w1.x); fma2(acc[0][1], x0.y, w1.y);
        fma2(acc[1][0], x1.x, w0.x); fma2(acc[1][1], x1.x, w0.y);
        fma2(acc[1][0], x1.y, w1.x); fma2(acc[1][1], x1.y, w1.y);
        fma2(acc[2][0], x2.x, w0.x); fma2(acc[2][1], x2.x, w0.y);
        fma2(acc[2][0], x2.y, w1.x); fma2(acc[2][1], x2.y, w1.y);
        fma2(acc[3][0], x3.x, w0.x); fma2(acc[3][1], x3.x, w0.y);
        fma2(acc[3][0], x3.y, w1.x); fma2(acc[3][1], x3.y, w1.y);
    }
}

__device__ __forceinline__ void biasp(ULL (&acc)[4][2], const float* b, int cg) {
    float2 v = *(const float2*)&b[cg * 2];
    ULL px = pk2(v.x, 0.f), py = pk2(v.y, 0.f);
    #pragma unroll
    for (int j = 0; j < 4; j++) { acc[j][0] = px; acc[j][1] = py; }
}

// ---------------------------------------------------------------------------
// prep: interleave 16 weight matrices (k-pairs adjacent per column)
//   g_Wi[m][(k>>1)*128 + c*2 + (k&1)] = Wsrc[k*64 + c]
// m = l*8 + {0:Wm0,1:Wm1,2:Ug0,3:Wg0,4:Ug1,5:Wg1,6:Ug2,7:Wg2}
// ---------------------------------------------------------------------------
__global__ void prep_weights(const float* __restrict__ W_msg,
                             const float* __restrict__ Wg,
                             const float* __restrict__ Ug) {
    int m = blockIdx.x, tid = threadIdx.x;
    int l = m >> 3, s = m & 7;
    const float* src;
    if (s < 2) src = W_msg + ((size_t)l * 2 + s) * 4096;
    else {
        int g = (s - 2) >> 1;
        bool isU = ((s - 2) & 1) == 0;
        src = (isU ? Ug : Wg) + ((size_t)l * 3 + g) * 4096;
    }
    float* dst = g_Wi + (size_t)m * 4096;
    #pragma unroll
    for (int i = 0; i < 4; i++) {
        int i4 = tid + i * 256;          // float4 index 0..1023
        int k = i4 >> 4, c4 = i4 & 15;
        float4 v = *(const float4*)(src + (size_t)k * 64 + c4 * 4);
        int base = (k >> 1) * 128 + (k & 1);
        dst[base + (c4 * 4 + 0) * 2] = v.x;
        dst[base + (c4 * 4 + 1) * 2] = v.y;
        dst[base + (c4 * 4 + 2) * 2] = v.z;
        dst[base + (c4 * 4 + 3) * 2] = v.w;
    }
}

// ---------------------------------------------------------------------------
__global__ void __cluster_dims__(4, 1, 1) __launch_bounds__(256, 1)
ggnn_all(const float* __restrict__ input_seq,
         const int* __restrict__ seq_lengths,
         const float* __restrict__ Adj,
         const float* __restrict__ b_msg,
         const float* __restrict__ bg,
         const float* __restrict__ fc_w,
         const float* __restrict__ fc_b,
         float* __restrict__ out)
{
    extern __shared__ float sm[];
    float* shi = sm + OFF_SHI;
    float* sA  = sm + OFF_SA;
    float* sho = sm + OFF_SHO;
    float* sM0 = sm + OFF_SM0;
    float* sM1 = sm + OFF_SM1;
    float* sa  = sm + OFF_SAa;
    float* sW0 = sm + OFF_SW0;
    float* sW1 = sm + OFF_SW1;

    const int tid   = threadIdx.x;
    const int rg    = tid >> 5;          // warp id 0..7 -> rows rg+8j
    const int cg    = tid & 31;          // col pair: cols 2cg, 2cg+1
    const int b     = blockIdx.x >> 2;
    const int crank = blockIdx.x & 3;
    const int r0    = crank * 32;

    const int rb0 = rg * 68;
    const int rb1 = (rg + 8) * 68;
    const int rb2 = (rg + 16) * 68;
    const int rb3 = (rg + 24) * 68;

    // ---------------- prologue ----------------
    {
        int idx = seq_lengths[b] - 1;
        idx = idx < 0 ? 0 : (idx > 31 ? 31 : idx);
        const float* src = input_seq + ((size_t)(b * 32 + idx)) * 8192 + (size_t)r0 * 64;
        float* dst = g_h + (size_t)b * 8192 + (size_t)r0 * 64;
        #pragma unroll
        for (int i = 0; i < 2; i++) {
            int i4 = tid + i * 256;              // 0..511: n = i4>>4, u4 = i4&15
            int n = i4 >> 4, u4 = i4 & 15;
            float4 v = *(const float4*)(src + (size_t)n * 64 + u4 * 4);
            __stcg((float4*)(dst + (size_t)n * 64 + u4 * 4), v);
            *(float4*)&sho[n * 68 + u4 * 4] = v;
        }
        // A[b][e][r0+r][:] -> sA[(e*32+r)*132 + k]
        #pragma unroll
        for (int i = 0; i < 8; i++) {
            int i4 = tid + i * 256;
            int e = i4 >> 10, r = (i4 >> 5) & 31, c4 = i4 & 31;
            float4 v = *(const float4*)(Adj +
                       (((size_t)b * 2 + e) * 128 + r0 + r) * 128 + c4 * 4);
            *(float4*)&sA[(e * 32 + r) * 132 + c4 * 4] = v;
        }
    }

    float2 hn[4];

    for (int l = 0; l < 2; l++) {
        const float* Wi  = g_Wi + (size_t)l * 8 * 4096;
        const float* bml = b_msg + l * 64;
        const float* bgl = bg + l * 192;

        for (int s = 0; s < 3; s++) {
            // -------- h exchange across cluster --------
            __threadfence();
            cl_sync();
            __threadfence();

            prefW(sW0, Wi + 0 * 4096, tid);            // G1: Wm0
            prefW(sW1, Wi + 1 * 4096, tid);            // G2: Wm1

            {   // read full h[b], write k-pair-interleaved into shi
                const float* hb = g_h + (size_t)b * 8192;
                #pragma unroll
                for (int i = 0; i < 4; i++) {
                    int t = tid + i * 256;             // 0..1023: n2, u4
                    int n2 = t >> 4, u4 = t & 15;
                    float4 v0 = __ldcg((const float4*)(hb + (size_t)(2 * n2) * 64 + u4 * 4));
                    float4 v1 = __ldcg((const float4*)(hb + (size_t)(2 * n2 + 1) * 64 + u4 * 4));
                    float* d = shi + n2 * 128 + u4 * 8;
                    *(ULL*)(d + 0) = pk2(v0.x, v1.x);
                    *(ULL*)(d + 2) = pk2(v0.y, v1.y);
                    *(ULL*)(d + 4) = pk2(v0.z, v1.z);
                    *(ULL*)(d + 6) = pk2(v0.w, v1.w);
                }
            }
            __syncthreads();                            // shi (and sA/sho 1st iter) visible

            // -------- msgmm: M_e = A_e @ h, packed along k --------
            {
                ULL acc[2][4][2] = {};                  // [edge][rowj][colpair]
                #pragma unroll 2
                for (int k2 = 0; k2 < 64; k2 += 2) {
                    ulonglong2 w0 = *(const ulonglong2*)(shi + k2 * 128 + cg * 4);
                    ulonglong2 w1 = *(const ulonglong2*)(shi + k2 * 128 + 128 + cg * 4);
                    #pragma unroll
                    for (int j = 0; j < 4; j++) {
                        int row = rg + 8 * j;
                        ulonglong2 a0 = *(const ulonglong2*)(sA + row * 132 + 2 * k2);
                        ulonglong2 a1 = *(const ulonglong2*)(sA + (32 + row) * 132 + 2 * k2);
                        fma2(acc[0][j][0], a0.x, w0.x); fma2(acc[0][j][1], a0.x, w0.y);
                        fma2(acc[0][j][0], a0.y, w1.x); fma2(acc[0][j][1], a0.y, w1.y);
                        fma2(acc[1][j][0], a1.x, w0.x); fma2(acc[1][j][1], a1.x, w0.y);
                        fma2(acc[1][j][0], a1.y, w1.x); fma2(acc[1][j][1], a1.y, w1.y);
                    }
                }
                #pragma unroll
                for (int j = 0; j < 4; j++) {
                    int rb = (rg + 8 * j) * 68 + cg * 2;
                    *(float2*)&sM0[rb] = make_float2(red2(acc[0][j][0]), red2(acc[0][j][1]));
                    *(float2*)&sM1[rb] = make_float2(red2(acc[1][j][0]), red2(acc[1][j][1]));
                }
            }
            CP_WAIT(1); __syncthreads();                // sM visible, sW0 (Wm0) ready

            float2 hv[4];
            hv[0] = *(const float2*)&sho[rb0 + cg * 2];
            hv[1] = *(const float2*)&sho[rb1 + cg * 2];
            hv[2] = *(const float2*)&sho[rb2 + cg * 2];
            hv[3] = *(const float2*)&sho[rb3 + cg * 2];

            // -------- a = M0@W0 + M1@W1 + b_msg --------
            ULL accA[4][2];
            biasp(accA, bml, cg);
            gemmp(accA, sM0, rb0, rb1, rb2, rb3, sW0, cg);
            __syncthreads();  prefW(sW0, Wi + 2 * 4096, tid);   // G3: Ug0
            CP_WAIT(1); __syncthreads();                        // sW1 (Wm1) ready
            gemmp(accA, sM1, rb0, rb1, rb2, rb3, sW1, cg);
            *(float2*)&sa[rb0 + cg * 2] = make_float2(red2(accA[0][0]), red2(accA[0][1]));
            *(float2*)&sa[rb1 + cg * 2] = make_float2(red2(accA[1][0]), red2(accA[1][1]));
            *(float2*)&sa[rb2 + cg * 2] = make_float2(red2(accA[2][0]), red2(accA[2][1]));
            *(float2*)&sa[rb3 + cg * 2] = make_float2(red2(accA[3][0]), red2(accA[3][1]));
            __syncthreads();  prefW(sW1, Wi + 3 * 4096, tid);   // G4: Wg0
            CP_WAIT(1); __syncthreads();                        // Ug0 ready, sa visible

            // -------- z = sigmoid(a@Wg0 + h@Ug0 + bg0) --------
            ULL accZ[4][2];
            biasp(accZ, bgl, cg);
            gemmp(accZ, sho, rb0, rb1, rb2, rb3, sW0, cg);
            __syncthreads();  prefW(sW0, Wi + 4 * 4096, tid);   // G5: Ug1
            CP_WAIT(1); __syncthreads();                        // Wg0 ready
            gemmp(accZ, sa, rb0, rb1, rb2, rb3, sW1, cg);
            float2 zz[4];
            #pragma unroll
            for (int j = 0; j < 4; j++) {
                zz[j].x = fsig(red2(accZ[j][0]));
                zz[j].y = fsig(red2(accZ[j][1]));
            }
            __syncthreads();  prefW(sW1, Wi + 5 * 4096, tid);   // G6: Wg1
            CP_WAIT(1); __syncthreads();                        // Ug1 ready

            // -------- r = sigmoid(a@Wg1 + h@Ug1 + bg1); rh = r*h --------
            ULL accR[4][2];
            biasp(accR, bgl + 64, cg);
            gemmp(accR, sho, rb0, rb1, rb2, rb3, sW0, cg);
            __syncthreads();  prefW(sW0, Wi + 6 * 4096, tid);   // G7: Ug2
            CP_WAIT(1); __syncthreads();                        // Wg1 ready
            gemmp(accR, sa, rb0, rb1, rb2, rb3, sW1, cg);
            {
                #pragma unroll
                for (int j = 0; j < 4; j++) {
                    float rx = fsig(red2(accR[j][0]));
                    float ry = fsig(red2(accR[j][1]));
                    *(float2*)&sM0[(rg + 8 * j) * 68 + cg * 2] =
                        make_float2(rx * hv[j].x, ry * hv[j].y);
                }
            }
            __syncthreads();  prefW(sW1, Wi + 7 * 4096, tid);   // G8: Wg2
            CP_WAIT(1); __syncthreads();                        // Ug2 ready, rh visible

            // -------- c = tanh(a@Wg2 + rh@Ug2 + bg2); h = (1-z)h + z c ----
            ULL accC[4][2];
            biasp(accC, bgl + 128, cg);
            gemmp(accC, sM0, rb0, rb1, rb2, rb3, sW0, cg);
            CP_WAIT(0); __syncthreads();                        // Wg2 ready
            gemmp(accC, sa, rb0, rb1, rb2, rb3, sW1, cg);

            float* hb = g_h + (size_t)b * 8192;
            #pragma unroll
            for (int j = 0; j < 4; j++) {
                float cx = ftanh(red2(accC[j][0]));
                float cy = ftanh(red2(accC[j][1]));
                hn[j].x = (1.0f - zz[j].x) * hv[j].x + zz[j].x * cx;
                hn[j].y = (1.0f - zz[j].y) * hv[j].y + zz[j].y * cy;
                *(float2*)&sho[(rg + 8 * j) * 68 + cg * 2] = hn[j];
                __stcg((float2*)&hb[(r0 + rg + 8 * j) * 64 + cg * 2], hn[j]);
            }
        }
    }

    // ---------------- final: relu -> fc -> max over nodes -----------------
    __syncthreads();                     // drain all smem readers
    #pragma unroll
    for (int j = 0; j < 4; j++)
        *(float2*)&sa[(rg + 8 * j) * 68 + cg * 2] = hn[j];
    for (int i = tid; i < 320; i += 256) sW0[i] = fc_w[i];
    __syncthreads();

    if (tid < 160) {
        int row = tid / 5, c = tid % 5;
        float acc = fc_b[c];
        #pragma unroll 8
        for (int u = 0; u < 64; u++) {
            float v = sa[row * 68 + u];
            v = v > 0.0f ? v : 0.0f;
            acc += v * sW0[u * 5 + c];
        }
        sM1[row * 5 + c] = acc;
    }
    __syncthreads();
    if (tid < 5) {
        float m = -1e30f;
        #pragma unroll 8
        for (int r = 0; r < 32; r++) m = fmaxf(m, sM1[r * 5 + tid]);
        __stcg(&g_part[(b * 4 + crank) * 5 + tid], m);
    }
    __threadfence();
    cl_sync();
    __threadfence();
    if (crank == 0 && tid < 5) {
        float m = -1e30f;
        #pragma unroll
        for (int r = 0; r < 4; r++)
            m = fmaxf(m, __ldcg(&g_part[(b * 4 + r) * 5 + tid]));
        out[b * 5 + tid] = m;
    }
}

// ---------------------------------------------------------------------------
extern "C" void kernel_launch(void* const* d_in, const int* in_sizes, int n_in,
                              void* d_out, int out_size) {
    const float* input_seq   = (const float*)d_in[0];
    const int*   seq_lengths = (const int*)d_in[1];
    const float* Adj         = (const float*)d_in[2];
    const float* W_msg       = (const float*)d_in[3];
    const float* b_msg       = (const float*)d_in[4];
    const float* Wg          = (const float*)d_in[5];
    const float* Ug          = (const float*)d_in[6];
    const float* bg          = (const float*)d_in[7];
    const float* fc_w        = (const float*)d_in[8];
    const float* fc_b        = (const float*)d_in[9];
    float* out = (float*)d_out;

    cudaFuncSetAttribute(ggnn_all,
                         cudaFuncAttributeMaxDynamicSharedMemorySize, SMEM_BYTES);

    prep_weights<<<16, 256>>>(W_msg, Wg, Ug);
    ggnn_all<<<128, 256, SMEM_BYTES>>>(input_seq, seq_lengths, Adj,
                                       b_msg, bg, fc_w, fc_b, out);
}

// round 17
// speedup vs baseline: 1.8667x; 1.1159x over previous
#include <cuda_runtime.h>
#include <cuda_bf16.h>
#include <math.h>

// B=32, S=32, N=128, U=64, E=2, L=2, N_STEPS=3, NC=5
typedef unsigned long long ULL;

// Scratch (allocation-free)
__device__ float g_h[32 * 128 * 64];     // hidden state, per batch
__device__ float g_part[32 * 4 * 5];     // per-CTA partial logit maxima
__device__ float g_Wi[16 * 4096];        // interleaved weights: [m][k2*128 + c*2 + p]

// ---------------- packed f32x2 helpers ----------------
__device__ __forceinline__ ULL pk2(float a, float b) {
    ULL r; asm("mov.b64 %0,{%1,%2};" : "=l"(r) : "f"(a), "f"(b)); return r;
}
__device__ __forceinline__ float2 upk2(ULL v) {
    float2 f; asm("mov.b64 {%0,%1},%2;" : "=f"(f.x), "=f"(f.y) : "l"(v)); return f;
}
__device__ __forceinline__ void fma2(ULL& d, ULL a, ULL b) {
    asm("fma.rn.f32x2 %0,%1,%2,%0;" : "+l"(d) : "l"(a), "l"(b));
}
__device__ __forceinline__ float red2(ULL v) { float2 f = upk2(v); return f.x + f.y; }
__device__ __forceinline__ float fsig(float x) {
    return __fdividef(1.0f, 1.0f + __expf(-x));
}
__device__ __forceinline__ float ftanh(float x) {
    return __fdividef(2.0f, 1.0f + __expf(-2.0f * x)) - 1.0f;
}

// smem layout (float offsets) — tiles unpadded (all reads are broadcasts)
#define OFF_SHI 0          // interleaved h  [64 k2][128]      8192
#define OFF_SA  8192       // A slice [2][32][128]             8192
#define OFF_SHO 16384      // own h rows [32][64]              2048
#define OFF_SM0 18432      // [32][64]                         2048
#define OFF_SM1 20480      // [32][64]                         2048
#define OFF_SAa 22528      // [32][64]                         2048
#define OFF_SW  24576      // 8 resident weight mats           32768
#define SMEM_FLOATS 57344
#define SMEM_BYTES (SMEM_FLOATS * 4)     // 229376 B <= 227KB opt-in

__device__ __forceinline__ void cpa16(float* s, const float* g) {
    unsigned a = (unsigned)__cvta_generic_to_shared(s);
    asm volatile("cp.async.cg.shared.global [%0], [%1], 16;" :: "r"(a), "l"(g));
}
#define CP_COMMIT() asm volatile("cp.async.commit_group;" ::: "memory")
#define CP_WAIT(n)  asm volatile("cp.async.wait_group %0;" :: "n"(n) : "memory")

__device__ __forceinline__ void cl_sync() {
    asm volatile("barrier.cluster.arrive.aligned;" ::: "memory");
    asm volatile("barrier.cluster.wait.aligned;" ::: "memory");
}

// acc[4][2] += t0 @ W0 + t1 @ W1 over k=64 (k2-packed, interleaved W layout)
__device__ __forceinline__ void gemm2W(ULL (&acc)[4][2],
                                       const float* __restrict__ t0,
                                       const float* __restrict__ t1,
                                       const float* __restrict__ W0,
                                       const float* __restrict__ W1,
                                       int rb0, int rb1, int rb2, int rb3, int cg) {
    #pragma unroll 4
    for (int k2 = 0; k2 < 32; k2 += 2) {
        ulonglong2 u0 = *(const ulonglong2*)(W0 + k2 * 128 + cg * 4);
        ulonglong2 u1 = *(const ulonglong2*)(W0 + k2 * 128 + 128 + cg * 4);
        ulonglong2 v0 = *(const ulonglong2*)(W1 + k2 * 128 + cg * 4);
        ulonglong2 v1 = *(const ulonglong2*)(W1 + k2 * 128 + 128 + cg * 4);
        #pragma unroll
        for (int j = 0; j < 4; j++) {
            int rb = (j == 0) ? rb0 : (j == 1) ? rb1 : (j == 2) ? rb2 : rb3;
            ulonglong2 x = *(const ulonglong2*)(t0 + rb + 2 * k2);
            ulonglong2 y = *(const ulonglong2*)(t1 + rb + 2 * k2);
            fma2(acc[j][0], x.x, u0.x); fma2(acc[j][1], x.x, u0.y);
            fma2(acc[j][0], x.y, u1.x); fma2(acc[j][1], x.y, u1.y);
            fma2(acc[j][0], y.x, v0.x); fma2(acc[j][1], y.x, v0.y);
            fma2(acc[j][0], y.y, v1.x); fma2(acc[j][1], y.y, v1.y);
        }
    }
}

// fused z/r: aZ += th@U0 + ta@G0 ; aR += th@U1 + ta@G1
__device__ __forceinline__ void gemmZR(ULL (&aZ)[4][2], ULL (&aR)[4][2],
                                       const float* __restrict__ th,
                                       const float* __restrict__ ta,
                                       const float* __restrict__ U0,
                                       const float* __restrict__ G0,
                                       const float* __restrict__ U1,
                                       const float* __restrict__ G1,
                                       int rb0, int rb1, int rb2, int rb3, int cg) {
    #pragma unroll 2
    for (int k2 = 0; k2 < 32; k2 += 2) {
        ulonglong2 u0a = *(const ulonglong2*)(U0 + k2 * 128 + cg * 4);
        ulonglong2 u0b = *(const ulonglong2*)(U0 + k2 * 128 + 128 + cg * 4);
        ulonglong2 g0a = *(const ulonglong2*)(G0 + k2 * 128 + cg * 4);
        ulonglong2 g0b = *(const ulonglong2*)(G0 + k2 * 128 + 128 + cg * 4);
        ulonglong2 u1a = *(const ulonglong2*)(U1 + k2 * 128 + cg * 4);
        ulonglong2 u1b = *(const ulonglong2*)(U1 + k2 * 128 + 128 + cg * 4);
        ulonglong2 g1a = *(const ulonglong2*)(G1 + k2 * 128 + cg * 4);
        ulonglong2 g1b = *(const ulonglong2*)(G1 + k2 * 128 + 128 + cg * 4);
        #pragma unroll
        for (int j = 0; j < 4; j++) {
            int rb = (j == 0) ? rb0 : (j == 1) ? rb1 : (j == 2) ? rb2 : rb3;
            ulonglong2 x = *(const ulonglong2*)(th + rb + 2 * k2);
            ulonglong2 y = *(const ulonglong2*)(ta + rb + 2 * k2);
            fma2(aZ[j][0], x.x, u0a.x); fma2(aZ[j][1], x.x, u0a.y);
            fma2(aZ[j][0], x.y, u0b.x); fma2(aZ[j][1], x.y, u0b.y);
            fma2(aZ[j][0], y.x, g0a.x); fma2(aZ[j][1], y.x, g0a.y);
            fma2(aZ[j][0], y.y, g0b.x); fma2(aZ[j][1], y.y, g0b.y);
            fma2(aR[j][0], x.x, u1a.x); fma2(aR[j][1], x.x, u1a.y);
            fma2(aR[j][0], x.y, u1b.x); fma2(aR[j][1], x.y, u1b.y);
            fma2(aR[j][0], y.x, g1a.x); fma2(aR[j][1], y.x, g1a.y);
            fma2(aR[j][0], y.y, g1b.x); fma2(aR[j][1], y.y, g1b.y);
        }
    }
}

__device__ __forceinline__ void biasp(ULL (&acc)[4][2], const float* b, int cg) {
    float2 v = *(const float2*)&b[cg * 2];
    ULL px = pk2(v.x, 0.f), py = pk2(v.y, 0.f);
    #pragma unroll
    for (int j = 0; j < 4; j++) { acc[j][0] = px; acc[j][1] = py; }
}

// ---------------------------------------------------------------------------
// prep: interleave 16 weight matrices (k-pairs adjacent per column)
//   g_Wi[m][(k>>1)*128 + c*2 + (k&1)] = Wsrc[k*64 + c]
// m = l*8 + {0:Wm0,1:Wm1,2:Ug0,3:Wg0,4:Ug1,5:Wg1,6:Ug2,7:Wg2}
// ---------------------------------------------------------------------------
__global__ void prep_weights(const float* __restrict__ W_msg,
                             const float* __restrict__ Wg,
                             const float* __restrict__ Ug) {
    int m = blockIdx.x, tid = threadIdx.x;
    int l = m >> 3, s = m & 7;
    const float* src;
    if (s < 2) src = W_msg + ((size_t)l * 2 + s) * 4096;
    else {
        int g = (s - 2) >> 1;
        bool isU = ((s - 2) & 1) == 0;
        src = (isU ? Ug : Wg) + ((size_t)l * 3 + g) * 4096;
    }
    float* dst = g_Wi + (size_t)m * 4096;
    #pragma unroll
    for (int i = 0; i < 4; i++) {
        int i4 = tid + i * 256;          // float4 index 0..1023
        int k = i4 >> 4, c4 = i4 & 15;
        float4 v = *(const float4*)(src + (size_t)k * 64 + c4 * 4);
        int base = (k >> 1) * 128 + (k & 1);
        dst[base + (c4 * 4 + 0) * 2] = v.x;
        dst[base + (c4 * 4 + 1) * 2] = v.y;
        dst[base + (c4 * 4 + 2) * 2] = v.z;
        dst[base + (c4 * 4 + 3) * 2] = v.w;
    }
}

// ---------------------------------------------------------------------------
__global__ void __cluster_dims__(4, 1, 1) __launch_bounds__(256, 1)
ggnn_all(const float* __restrict__ input_seq,
         const int* __restrict__ seq_lengths,
         const float* __restrict__ Adj,
         const float* __restrict__ b_msg,
         const float* __restrict__ bg,
         const float* __restrict__ fc_w,
         const float* __restrict__ fc_b,
         float* __restrict__ out)
{
    extern __shared__ float sm[];
    float* shi = sm + OFF_SHI;
    float* sA  = sm + OFF_SA;
    float* sho = sm + OFF_SHO;
    float* sM0 = sm + OFF_SM0;
    float* sM1 = sm + OFF_SM1;
    float* sa  = sm + OFF_SAa;
    float* sW  = sm + OFF_SW;

    const int tid   = threadIdx.x;
    const int rg    = tid >> 5;          // warp id 0..7 -> rows rg+8j
    const int cg    = tid & 31;          // col pair: cols 2cg, 2cg+1
    const int b     = blockIdx.x >> 2;
    const int crank = blockIdx.x & 3;
    const int r0    = crank * 32;

    const int rb0 = rg * 64;
    const int rb1 = (rg + 8) * 64;
    const int rb2 = (rg + 16) * 64;
    const int rb3 = (rg + 24) * 64;

    // ---------------- prologue ----------------
    {
        int idx = seq_lengths[b] - 1;
        idx = idx < 0 ? 0 : (idx > 31 ? 31 : idx);
        const float* src = input_seq + ((size_t)(b * 32 + idx)) * 8192 + (size_t)r0 * 64;
        float* dst = g_h + (size_t)b * 8192 + (size_t)r0 * 64;
        #pragma unroll
        for (int i = 0; i < 2; i++) {
            int i4 = tid + i * 256;              // 0..511
            float4 v = *(const float4*)(src + (size_t)i4 * 4);
            __stcg((float4*)(dst + (size_t)i4 * 4), v);
            *(float4*)&sho[i4 * 4] = v;          // stride 64 == dense
        }
        // A[b][e][r0+r][:] -> sA[(e*32+r)*128 + k]
        #pragma unroll
        for (int i = 0; i < 8; i++) {
            int i4 = tid + i * 256;
            int e = i4 >> 10, r = (i4 >> 5) & 31, c4 = i4 & 31;
            float4 v = *(const float4*)(Adj +
                       (((size_t)b * 2 + e) * 128 + r0 + r) * 128 + c4 * 4);
            *(float4*)&sA[(e * 32 + r) * 128 + c4 * 4] = v;
        }
    }

    float2 hn[4];

    for (int l = 0; l < 2; l++) {
        const float* Wi  = g_Wi + (size_t)l * 8 * 4096;
        const float* bml = b_msg + l * 64;
        const float* bgl = bg + l * 192;

        for (int s = 0; s < 3; s++) {
            // -------- h exchange across cluster (also full CTA barrier) ----
            __threadfence();
            cl_sync();
            __threadfence();

            if (s == 0) {   // stage this layer's 8 weight matrices (128 KB)
                #pragma unroll
                for (int i = 0; i < 32; i++) {
                    int o = (tid + i * 256) * 4;
                    cpa16(sW + o, Wi + o);
                }
                CP_COMMIT();
            }

            {   // read full h[b], write k-pair-interleaved into shi
                const float* hb = g_h + (size_t)b * 8192;
                #pragma unroll
                for (int i = 0; i < 4; i++) {
                    int t = tid + i * 256;             // 0..1023: n2, u4
                    int n2 = t >> 4, u4 = t & 15;
                    float4 v0 = __ldcg((const float4*)(hb + (size_t)(2 * n2) * 64 + u4 * 4));
                    float4 v1 = __ldcg((const float4*)(hb + (size_t)(2 * n2 + 1) * 64 + u4 * 4));
                    float* d = shi + n2 * 128 + u4 * 8;
                    ulonglong2 p0, p1;
                    p0.x = pk2(v0.x, v1.x); p0.y = pk2(v0.y, v1.y);
                    p1.x = pk2(v0.z, v1.z); p1.y = pk2(v0.w, v1.w);
                    *(ulonglong2*)(d + 0) = p0;
                    *(ulonglong2*)(d + 4) = p1;
                }
            }
            if (s == 0) { CP_WAIT(0); }
            __syncthreads();            // shi + (s==0) weights visible to all

            // -------- msgmm: M_e = A_e @ h, packed along k --------
            {
                ULL acc[2][4][2] = {};                  // [edge][rowj][col]
                #pragma unroll 2
                for (int k2 = 0; k2 < 64; k2 += 2) {
                    ulonglong2 w0 = *(const ulonglong2*)(shi + k2 * 128 + cg * 4);
                    ulonglong2 w1 = *(const ulonglong2*)(shi + k2 * 128 + 128 + cg * 4);
                    #pragma unroll
                    for (int j = 0; j < 4; j++) {
                        int row = rg + 8 * j;
                        ulonglong2 a0 = *(const ulonglong2*)(sA + row * 128 + 2 * k2);
                        ulonglong2 a1 = *(const ulonglong2*)(sA + (32 + row) * 128 + 2 * k2);
                        fma2(acc[0][j][0], a0.x, w0.x); fma2(acc[0][j][1], a0.x, w0.y);
                        fma2(acc[0][j][0], a0.y, w1.x); fma2(acc[0][j][1], a0.y, w1.y);
                        fma2(acc[1][j][0], a1.x, w0.x); fma2(acc[1][j][1], a1.x, w0.y);
                        fma2(acc[1][j][0], a1.y, w1.x); fma2(acc[1][j][1], a1.y, w1.y);
                    }
                }
                #pragma unroll
                for (int j = 0; j < 4; j++) {
                    int rb = (rg + 8 * j) * 64 + cg * 2;
                    *(float2*)&sM0[rb] = make_float2(red2(acc[0][j][0]), red2(acc[0][j][1]));
                    *(float2*)&sM1[rb] = make_float2(red2(acc[1][j][0]), red2(acc[1][j][1]));
                }
            }
            __syncwarp();               // tiles are warp-private rows

            float2 hv[4];
            hv[0] = *(const float2*)&sho[rb0 + cg * 2];
            hv[1] = *(const float2*)&sho[rb1 + cg * 2];
            hv[2] = *(const float2*)&sho[rb2 + cg * 2];
            hv[3] = *(const float2*)&sho[rb3 + cg * 2];

            // -------- a = M0@Wm0 + M1@Wm1 + b_msg (fused) --------
            ULL accA[4][2];
            biasp(accA, bml, cg);
            gemm2W(accA, sM0, sM1, sW, sW + 4096, rb0, rb1, rb2, rb3, cg);
            *(float2*)&sa[rb0 + cg * 2] = make_float2(red2(accA[0][0]), red2(accA[0][1]));
            *(float2*)&sa[rb1 + cg * 2] = make_float2(red2(accA[1][0]), red2(accA[1][1]));
            *(float2*)&sa[rb2 + cg * 2] = make_float2(red2(accA[2][0]), red2(accA[2][1]));
            *(float2*)&sa[rb3 + cg * 2] = make_float2(red2(accA[3][0]), red2(accA[3][1]));
            __syncwarp();

            // -------- z,r = sigmoid(h@Ug{0,1} + a@Wg{0,1} + bg{0,1}) fused -
            ULL accZ[4][2], accR[4][2];
            biasp(accZ, bgl, cg);
            biasp(accR, bgl + 64, cg);
            gemmZR(accZ, accR, sho, sa,
                   sW + 2 * 4096, sW + 3 * 4096,   // Ug0, Wg0
                   sW + 4 * 4096, sW + 5 * 4096,   // Ug1, Wg1
                   rb0, rb1, rb2, rb3, cg);
            float2 zz[4];
            #pragma unroll
            for (int j = 0; j < 4; j++) {
                zz[j].x = fsig(red2(accZ[j][0]));
                zz[j].y = fsig(red2(accZ[j][1]));
                float rx = fsig(red2(accR[j][0]));
                float ry = fsig(red2(accR[j][1]));
                *(float2*)&sM0[(rg + 8 * j) * 64 + cg * 2] =
                    make_float2(rx * hv[j].x, ry * hv[j].y);   // rh tile
            }
            __syncwarp();

            // -------- c = tanh(rh@Ug2 + a@Wg2 + bg2); h = (1-z)h + z c -----
            ULL accC[4][2];
            biasp(accC, bgl + 128, cg);
            gemm2W(accC, sM0, sa, sW + 6 * 4096, sW + 7 * 4096,
                   rb0, rb1, rb2, rb3, cg);

            float* hb = g_h + (size_t)b * 8192;
            #pragma unroll
            for (int j = 0; j < 4; j++) {
                float cx = ftanh(red2(accC[j][0]));
                float cy = ftanh(red2(accC[j][1]));
                hn[j].x = (1.0f - zz[j].x) * hv[j].x + zz[j].x * cx;
                hn[j].y = (1.0f - zz[j].y) * hv[j].y + zz[j].y * cy;
                *(float2*)&sho[(rg + 8 * j) * 64 + cg * 2] = hn[j];
                __stcg((float2*)&hb[(r0 + rg + 8 * j) * 64 + cg * 2], hn[j]);
            }
        }
    }

    // ---------------- final: relu -> fc -> max over nodes -----------------
    __syncthreads();                     // all warps done with sW / tiles
    #pragma unroll
    for (int j = 0; j < 4; j++)
        *(float2*)&sa[(rg + 8 * j) * 64 + cg * 2] = hn[j];
    for (int i = tid; i < 320; i += 256) sW[i] = fc_w[i];
    __syncthreads();

    if (tid < 160) {
        int row = tid / 5, c = tid % 5;
        float acc = fc_b[c];
        #pragma unroll 8
        for (int u = 0; u < 64; u++) {
            float v = sa[row * 64 + u];
            v = v > 0.0f ? v : 0.0f;
            acc += v * sW[u * 5 + c];
        }
        sM1[row * 5 + c] = acc;
    }
    __syncthreads();
    if (tid < 5) {
        float m = -1e30f;
        #pragma unroll 8
        for (int r = 0; r < 32; r++) m = fmaxf(m, sM1[r * 5 + tid]);
        __stcg(&g_part[(b * 4 + crank) * 5 + tid], m);
    }
    __threadfence();
    cl_sync();
    __threadfence();
    if (crank == 0 && tid < 5) {
        float m = -1e30f;
        #pragma unroll
        for (int r = 0; r < 4; r++)
            m = fmaxf(m, __ldcg(&g_part[(b * 4 + r) * 5 + tid]));
        out[b * 5 + tid] = m;
    }
}

// ---------------------------------------------------------------------------
extern "C" void kernel_launch(void* const* d_in, const int* in_sizes, int n_in,
                              void* d_out, int out_size) {
    const float* input_seq   = (const float*)d_in[0];
    const int*   seq_lengths = (const int*)d_in[1];
    const float* Adj         = (const float*)d_in[2];
    const float* W_msg       = (const float*)d_in[3];
    const float* b_msg       = (const float*)d_in[4];
    const float* Wg          = (const float*)d_in[5];
    const float* Ug          = (const float*)d_in[6];
    const float* bg          = (const float*)d_in[7];
    const float* fc_w        = (const float*)d_in[8];
    const float* fc_b        = (const float*)d_in[9];
    float* out = (float*)d_out;

    cudaFuncSetAttribute(ggnn_all,
                         cudaFuncAttributeMaxDynamicSharedMemorySize, SMEM_BYTES);

    prep_weights<<<16, 256>>>(W_msg, Wg, Ug);
    ggnn_all<<<128, 256, SMEM_BYTES>>>(input_seq, seq_lengths, Adj,
                                       b_msg, bg, fc_w, fc_b, out);
}